// round 8
// baseline (speedup 1.0000x reference)
#include <cuda_runtime.h>
#include <cuda_bf16.h>
#include <cstdint>

// ---------------- scratch ----------------
#define UV_MAX_ROWS 131072
__device__ float g_uv[(size_t)UV_MAX_ROWS * 512];
// W1 split into bf16 hi/lo, K-major: [half][n(256)][k(128)]
__device__ __nv_bfloat16 g_bhi[2][256][128];
__device__ __nv_bfloat16 g_blo[2][256][128];

__device__ __forceinline__ uint32_t smem_u32(const void* p) {
    uint32_t a;
    asm("{ .reg .u64 t; cvta.to.shared.u64 t, %1; cvt.u32.u64 %0, t; }" : "=r"(a) : "l"(p));
    return a;
}
__device__ __forceinline__ void ldm_x4(uint32_t* r, uint32_t addr) {
    asm volatile("ldmatrix.sync.aligned.m8n8.x4.shared.b16 {%0,%1,%2,%3}, [%4];"
                 : "=r"(r[0]), "=r"(r[1]), "=r"(r[2]), "=r"(r[3]) : "r"(addr));
}
__device__ __forceinline__ void ldm_x2(uint32_t* r, uint32_t addr) {
    asm volatile("ldmatrix.sync.aligned.m8n8.x2.shared.b16 {%0,%1}, [%2];"
                 : "=r"(r[0]), "=r"(r[1]) : "r"(addr));
}
__device__ __forceinline__ void mma_bf16(float* c, const uint32_t* a, const uint32_t* b) {
    asm volatile("mma.sync.aligned.m16n8k16.row.col.f32.bf16.bf16.f32 "
                 "{%0,%1,%2,%3}, {%4,%5,%6,%7}, {%8,%9}, {%0,%1,%2,%3};"
                 : "+f"(c[0]), "+f"(c[1]), "+f"(c[2]), "+f"(c[3])
                 : "r"(a[0]), "r"(a[1]), "r"(a[2]), "r"(a[3]), "r"(b[0]), "r"(b[1]));
}

// SMEM: bf16 tiles with 272-byte row pitch (128 k-elems = 256B + 16B pad).
// 272 mod 128 = 16 -> consecutive rows land on distinct 16B bank slots ->
// ldmatrix (8 rows/matrix) is conflict-free without swizzle.
#define PITCH 272
#define SM_AHI 0u
#define SM_ALO 34816u
#define SM_BHI 69632u
#define SM_BLO 104448u
#define SM_TOTAL 139264

// ---------------------------------------------------------------------------
// Kernel 0: split W1 into bf16 hi/lo K-major scratch (one shot, tiny).
// g_b*[half][n][k] = split of W1[(half*128 + k)*256 + n]
// ---------------------------------------------------------------------------
__global__ void bsplit_kernel(const float* __restrict__ W1)
{
    int idx  = blockIdx.x * 256 + threadIdx.x;     // 0..65535
    int half = idx >> 15;
    int k    = (idx >> 8) & 127;
    int n    = idx & 255;
    float v = W1[(half * 128 + k) * 256 + n];
    __nv_bfloat16 hi = __float2bfloat16(v);
    __nv_bfloat16 lo = __float2bfloat16(v - __bfloat162float(hi));
    g_bhi[half][n][k] = hi;
    g_blo[half][n][k] = lo;
}

// ---------------------------------------------------------------------------
// Kernel 1: split-bf16 GEMM via mma.sync.  Per CTA: 128 M-rows x 128 N-cols.
// C = Ahi*Bhi + Ahi*Blo + Alo*Bhi  (fp32 accum; lo*lo dropped ~2^-18 rel).
// grid.x = nblk 0..3 (N=512: 0,1 -> U cols with b1 fold; 2,3 -> V cols).
// 8 warps: warp (mw = wid&1, nw = wid>>1) owns 64x32 of C.
// ---------------------------------------------------------------------------
__global__ __launch_bounds__(256, 1)
void uv_mma_kernel(const float* __restrict__ A,
                   const float* __restrict__ b1,
                   int M)
{
    extern __shared__ char smem[];
    const uint32_t sb = smem_u32(smem);
    const int tid  = threadIdx.x;
    const int wid  = tid >> 5;
    const int lane = tid & 31;
    const int nblk = blockIdx.x;
    const int m0   = blockIdx.y * 128;
    const int half  = nblk >> 1;
    const int nbase = (nblk & 1) * 128;

    // ---- A tile: load fp32, split bf16 hi/lo, store padded rows ----
    for (int i = tid; i < 4096; i += 256) {
        const int m  = i >> 5;
        const int k0 = (i & 31) * 4;
        float4 v = make_float4(0.f, 0.f, 0.f, 0.f);
        if (m0 + m < M) v = *(const float4*)(A + (size_t)(m0 + m) * 128 + k0);
        __nv_bfloat162 h01 = __floats2bfloat162_rn(v.x, v.y);
        __nv_bfloat162 h23 = __floats2bfloat162_rn(v.z, v.w);
        __nv_bfloat162 l01 = __floats2bfloat162_rn(
            v.x - __bfloat162float(__low2bfloat16(h01)),
            v.y - __bfloat162float(__high2bfloat16(h01)));
        __nv_bfloat162 l23 = __floats2bfloat162_rn(
            v.z - __bfloat162float(__low2bfloat16(h23)),
            v.w - __bfloat162float(__high2bfloat16(h23)));
        uint2 ph, pl;
        ph.x = *(uint32_t*)&h01; ph.y = *(uint32_t*)&h23;
        pl.x = *(uint32_t*)&l01; pl.y = *(uint32_t*)&l23;
        const uint32_t off = m * PITCH + k0 * 2;
        *(uint2*)(smem + SM_AHI + off) = ph;
        *(uint2*)(smem + SM_ALO + off) = pl;
    }

    // ---- B tile: copy pre-split bf16 hi/lo (rows = n, K-major) ----
    for (int i = tid; i < 4096; i += 256) {
        const int n  = i >> 5;
        const int k0 = (i & 31) * 4;
        const uint32_t off = n * PITCH + k0 * 2;
        *(uint2*)(smem + SM_BHI + off) = *(const uint2*)&g_bhi[half][nbase + n][k0];
        *(uint2*)(smem + SM_BLO + off) = *(const uint2*)&g_blo[half][nbase + n][k0];
    }
    __syncthreads();

    const int mw = wid & 1;        // 0..1 (64 rows each)
    const int nw = wid >> 1;       // 0..3 (32 cols each)

    float acc[4][4][4];
    #pragma unroll
    for (int i = 0; i < 4; i++)
        #pragma unroll
        for (int j = 0; j < 4; j++)
            #pragma unroll
            for (int q = 0; q < 4; q++) acc[i][j][q] = 0.f;

    // ldmatrix lane address geometry
    // A x4: matrix = lane>>3: m_off = ((mat&1)<<3)+(lane&7), k_extra = (mat>>1)*16B
    const int amat = lane >> 3;
    const int aRow = ((amat & 1) << 3) + (lane & 7);
    const uint32_t aKx = (uint32_t)(amat >> 1) << 4;
    uint32_t aAddrH[4], aAddrL[4];
    #pragma unroll
    for (int mf = 0; mf < 4; mf++) {
        const uint32_t roff = (uint32_t)(mw * 64 + mf * 16 + aRow) * PITCH + aKx;
        aAddrH[mf] = sb + SM_AHI + roff;
        aAddrL[mf] = sb + SM_ALO + roff;
    }
    // B x2: matrices [n0-7, k0-7], [n0-7, k8-15]
    const int bmat = (lane >> 3) & 1;
    const int bRow = lane & 7;
    const uint32_t bKx = (uint32_t)bmat << 4;
    uint32_t bAddrH[4], bAddrL[4];
    #pragma unroll
    for (int nf = 0; nf < 4; nf++) {
        const uint32_t roff = (uint32_t)(nw * 32 + nf * 8 + bRow) * PITCH + bKx;
        bAddrH[nf] = sb + SM_BHI + roff;
        bAddrL[nf] = sb + SM_BLO + roff;
    }

    #pragma unroll 1
    for (int ks = 0; ks < 8; ks++) {       // K = 8 steps of 16
        const uint32_t kb = (uint32_t)ks * 32;   // 16 bf16 = 32 bytes
        uint32_t ah[4][4], al[4][4], bh[4][2], bl[4][2];
        #pragma unroll
        for (int mf = 0; mf < 4; mf++) {
            ldm_x4(ah[mf], aAddrH[mf] + kb);
            ldm_x4(al[mf], aAddrL[mf] + kb);
        }
        #pragma unroll
        for (int nf = 0; nf < 4; nf++) {
            ldm_x2(bh[nf], bAddrH[nf] + kb);
            ldm_x2(bl[nf], bAddrL[nf] + kb);
        }
        #pragma unroll
        for (int mf = 0; mf < 4; mf++)
            #pragma unroll
            for (int nf = 0; nf < 4; nf++) {
                mma_bf16(acc[mf][nf], ah[mf], bh[nf]);
                mma_bf16(acc[mf][nf], ah[mf], bl[nf]);
                mma_bf16(acc[mf][nf], al[mf], bh[nf]);
            }
    }

    // ---- epilogue: write C (+ b1 fold for U half) ----
    const int rbase = m0 + mw * 64 + (lane >> 2);
    const int cq    = (lane & 3) * 2;
    #pragma unroll
    for (int mf = 0; mf < 4; mf++) {
        #pragma unroll
        for (int nf = 0; nf < 4; nf++) {
            const int gcol = nblk * 128 + nw * 32 + nf * 8 + cq;
            float2 bb = make_float2(0.f, 0.f);
            if (nblk < 2) bb = *(const float2*)(b1 + gcol);
            const int r0 = rbase + mf * 16;
            if (r0 < M) {
                float2 o = make_float2(acc[mf][nf][0] + bb.x, acc[mf][nf][1] + bb.y);
                *(float2*)(g_uv + (size_t)r0 * 512 + gcol) = o;
            }
            if (r0 + 8 < M) {
                float2 o = make_float2(acc[mf][nf][2] + bb.x, acc[mf][nf][3] + bb.y);
                *(float2*)(g_uv + (size_t)(r0 + 8) * 512 + gcol) = o;
            }
        }
    }
}

// ---------------------------------------------------------------------------
// Kernel 2: per-edge MLP tail (unchanged, ~130 us, near traffic floor).
// ---------------------------------------------------------------------------
__global__ __launch_bounds__(256)
void edge_mlp_kernel(const int* __restrict__ ei,
                     const float* __restrict__ W2,
                     const float* __restrict__ b2,
                     float* __restrict__ out, int E, int N)
{
    __shared__ float4 sW2[64];
    const int tid = threadIdx.x;
    if (tid < 64) sW2[tid] = ((const float4*)W2)[tid];
    __syncthreads();

    const int e = blockIdx.x * 8 + (tid >> 5);
    if (e >= E) return;
    const int lane = tid & 31;

    int r = ei[e];
    int c = ei[E + e];
    const int hi = N - 1;
    r = r < 0 ? 0 : (r > hi ? hi : r);
    c = c < 0 ? 0 : (c > hi ? hi : c);

    const float4* u4 = (const float4*)(g_uv + (size_t)r * 512);
    const float4* v4 = (const float4*)(g_uv + (size_t)c * 512 + 256);

    float acc = 0.f;
    #pragma unroll
    for (int i = 0; i < 2; i++) {
        const int j = lane + 32 * i;
        const float4 u = u4[j];
        const float4 v = v4[j];
        const float4 w = sW2[j];
        acc = fmaf(fmaxf(u.x + v.x, 0.f), w.x, acc);
        acc = fmaf(fmaxf(u.y + v.y, 0.f), w.y, acc);
        acc = fmaf(fmaxf(u.z + v.z, 0.f), w.z, acc);
        acc = fmaf(fmaxf(u.w + v.w, 0.f), w.w, acc);
    }

    #pragma unroll
    for (int off = 16; off; off >>= 1)
        acc += __shfl_xor_sync(0xFFFFFFFFu, acc, off);

    if (lane == 0) {
        float w = fmaxf(acc + b2[0], 0.f);
        out[e] = (w < 0.05f) ? 0.f : w;
    }
}

// ---------------------------------------------------------------------------
// Host (proven size-based input mapping from R5).
// ---------------------------------------------------------------------------
extern "C" void kernel_launch(void* const* d_in, const int* in_sizes, int n_in,
                              void* d_out, int out_size)
{
    int ord[16];
    for (int i = 0; i < n_in; i++) ord[i] = i;
    for (int i = 0; i < n_in; i++)
        for (int j = i + 1; j < n_in; j++)
            if (in_sizes[ord[j]] > in_sizes[ord[i]]) { int t = ord[i]; ord[i] = ord[j]; ord[j] = t; }

    const int idx_emb = ord[0];
    const int idx_ei  = ord[1];
    const int idx_W1  = ord[2];
    const int idx_b2  = ord[n_in - 1];
    int idx_b1 = -1, idx_W2 = -1;
    for (int i = 0; i < n_in; i++) {
        if (i == idx_emb || i == idx_ei || i == idx_W1 || i == idx_b2) continue;
        if (idx_b1 < 0) idx_b1 = i; else idx_W2 = i;
    }

    const float* emb = (const float*)d_in[idx_emb];  // [N,128]
    const int*   ei  = (const int*)d_in[idx_ei];     // [2,E] int32
    const float* W1  = (const float*)d_in[idx_W1];   // [256,256]
    const float* b1  = (const float*)d_in[idx_b1];   // [256]
    const float* W2  = (const float*)d_in[idx_W2];   // [256,1]
    const float* b2  = (const float*)d_in[idx_b2];   // [1]
    float*       out = (float*)d_out;

    int N = in_sizes[idx_emb] / 128;
    if (N > UV_MAX_ROWS) N = UV_MAX_ROWS;
    const int E = in_sizes[idx_ei] / 2;

    cudaFuncSetAttribute(uv_mma_kernel,
                         cudaFuncAttributeMaxDynamicSharedMemorySize, SM_TOTAL);

    bsplit_kernel<<<256, 256>>>(W1);

    dim3 ggrid(4, (N + 127) / 128);
    uv_mma_kernel<<<ggrid, 256, SM_TOTAL>>>(emb, b1, N);

    const int blocks = (E + 7) / 8;
    edge_mlp_kernel<<<blocks, 256>>>(ei, W2, b2, out, E, N);
}

// round 11
// speedup vs baseline: 1.2151x; 1.2151x over previous
#include <cuda_runtime.h>
#include <cuda_bf16.h>
#include <cstdint>

// ---------------- scratch ----------------
#define UV_MAX_ROWS 131072
__device__ float g_uv[(size_t)UV_MAX_ROWS * 512];
// W1 split bf16 hi/lo, K-major: [half][n(256)][k(128)]
__device__ __nv_bfloat16 g_bhi[2][256][128];
__device__ __nv_bfloat16 g_blo[2][256][128];
// A (emb) split bf16 hi/lo, row-major [row][k(128)]
__device__ __nv_bfloat16 g_ahi[UV_MAX_ROWS][128];
__device__ __nv_bfloat16 g_alo[UV_MAX_ROWS][128];

__device__ __forceinline__ uint32_t smem_u32(const void* p) {
    uint32_t a;
    asm("{ .reg .u64 t; cvta.to.shared.u64 t, %1; cvt.u32.u64 %0, t; }" : "=r"(a) : "l"(p));
    return a;
}
__device__ __forceinline__ void cp16(uint32_t dst, const void* src) {
    asm volatile("cp.async.cg.shared.global [%0], [%1], 16;" :: "r"(dst), "l"(src));
}
__device__ __forceinline__ void cp_commit_wait() {
    asm volatile("cp.async.commit_group;" ::: "memory");
    asm volatile("cp.async.wait_group 0;" ::: "memory");
}
__device__ __forceinline__ void ldm_x4(uint32_t* r, uint32_t addr) {
    asm volatile("ldmatrix.sync.aligned.m8n8.x4.shared.b16 {%0,%1,%2,%3}, [%4];"
                 : "=r"(r[0]), "=r"(r[1]), "=r"(r[2]), "=r"(r[3]) : "r"(addr));
}
__device__ __forceinline__ void ldm_x2(uint32_t* r, uint32_t addr) {
    asm volatile("ldmatrix.sync.aligned.m8n8.x2.shared.b16 {%0,%1}, [%2];"
                 : "=r"(r[0]), "=r"(r[1]) : "r"(addr));
}
__device__ __forceinline__ void mma_bf16(float* c, const uint32_t* a, const uint32_t* b) {
    asm volatile("mma.sync.aligned.m16n8k16.row.col.f32.bf16.bf16.f32 "
                 "{%0,%1,%2,%3}, {%4,%5,%6,%7}, {%8,%9}, {%0,%1,%2,%3};"
                 : "+f"(c[0]), "+f"(c[1]), "+f"(c[2]), "+f"(c[3])
                 : "r"(a[0]), "r"(a[1]), "r"(a[2]), "r"(a[3]), "r"(b[0]), "r"(b[1]));
}

// SMEM: bf16 tiles, 272-byte row pitch (256B data + 16B pad => conflict-free ldmatrix)
#define PITCH 272
#define SM_AHI 0u
#define SM_ALO 17408u
#define SM_BHI 34816u
#define SM_BLO 69632u
#define SM_TOTAL 104448

// ---------------------------------------------------------------------------
// Kernel 0a: split W1 -> bf16 hi/lo K-major (one shot).
// ---------------------------------------------------------------------------
__global__ void bsplit_kernel(const float* __restrict__ W1)
{
    int idx  = blockIdx.x * 256 + threadIdx.x;     // 0..65535
    int half = idx >> 15;
    int k    = (idx >> 8) & 127;
    int n    = idx & 255;
    float v = W1[(half * 128 + k) * 256 + n];
    __nv_bfloat16 hi = __float2bfloat16(v);
    __nv_bfloat16 lo = __float2bfloat16(v - __bfloat162float(hi));
    g_bhi[half][n][k] = hi;
    g_blo[half][n][k] = lo;
}

// ---------------------------------------------------------------------------
// Kernel 0b: split A (emb) -> bf16 hi/lo row-major. One float4 per thread.
// ---------------------------------------------------------------------------
__global__ void asplit_kernel(const float* __restrict__ A, int M)
{
    int idx = blockIdx.x * 256 + threadIdx.x;      // over M*32 float4 groups
    if (idx >= M * 32) return;
    int row = idx >> 5;
    int k0  = (idx & 31) * 4;
    float4 v = *(const float4*)(A + (size_t)row * 128 + k0);
    __nv_bfloat162 h01 = __floats2bfloat162_rn(v.x, v.y);
    __nv_bfloat162 h23 = __floats2bfloat162_rn(v.z, v.w);
    __nv_bfloat162 l01 = __floats2bfloat162_rn(
        v.x - __bfloat162float(__low2bfloat16(h01)),
        v.y - __bfloat162float(__high2bfloat16(h01)));
    __nv_bfloat162 l23 = __floats2bfloat162_rn(
        v.z - __bfloat162float(__low2bfloat16(h23)),
        v.w - __bfloat162float(__high2bfloat16(h23)));
    uint2 ph, pl;
    ph.x = *(uint32_t*)&h01; ph.y = *(uint32_t*)&h23;
    pl.x = *(uint32_t*)&l01; pl.y = *(uint32_t*)&l23;
    *(uint2*)&g_ahi[row][k0] = ph;
    *(uint2*)&g_alo[row][k0] = pl;
}

// ---------------------------------------------------------------------------
// Kernel 1: split-bf16 GEMM via mma.sync.  CTA tile: 64 M-rows x 128 N-cols.
// C = Ahi*Bhi + Ahi*Blo + Alo*Bhi (fp32 accum). 102KB smem -> 2 CTAs/SM.
// grid.x = nblk 0..3 (cols 0..511; nblk<2 -> U with b1 fold).
// 8 warps: warp (mw = wid&1 -> 32 rows, nw = wid>>1 -> 32 cols).
// ---------------------------------------------------------------------------
__global__ __launch_bounds__(256, 2)
void uv_mma_kernel(const float* __restrict__ b1, int M)
{
    extern __shared__ char smem[];
    const uint32_t sb = smem_u32(smem);
    const int tid  = threadIdx.x;
    const int wid  = tid >> 5;
    const int lane = tid & 31;
    const int nblk = blockIdx.x;
    const int m0   = blockIdx.y * 64;
    const int half  = nblk >> 1;
    const int nbase = (nblk & 1) * 128;

    // ---- cp.async tile loads (bf16, pre-split) ----
    // A: 64 rows x 16 x 16B, hi+lo = 2048 chunks
    for (int i = tid; i < 2048; i += 256) {
        const int h   = i >> 10;           // 0 = hi, 1 = lo
        const int row = (i >> 4) & 63;
        const int q   = i & 15;
        const uint32_t dst = sb + (h ? SM_ALO : SM_AHI) + row * PITCH + q * 16;
        const __nv_bfloat16* src = (h ? g_alo : g_ahi)[m0 + row] + q * 8;
        cp16(dst, src);
    }
    // B: 128 rows x 16 x 16B, hi+lo = 4096 chunks
    for (int i = tid; i < 4096; i += 256) {
        const int h = i >> 11;
        const int n = (i >> 4) & 127;
        const int q = i & 15;
        const uint32_t dst = sb + (h ? SM_BLO : SM_BHI) + n * PITCH + q * 16;
        const __nv_bfloat16* src = (h ? g_blo : g_bhi)[half][nbase + n] + q * 8;
        cp16(dst, src);
    }
    cp_commit_wait();
    __syncthreads();

    const int mw = wid & 1;        // 32 rows each
    const int nw = wid >> 1;       // 32 cols each

    float acc[2][4][4];
    #pragma unroll
    for (int i = 0; i < 2; i++)
        #pragma unroll
        for (int j = 0; j < 4; j++)
            #pragma unroll
            for (int q = 0; q < 4; q++) acc[i][j][q] = 0.f;

    // ldmatrix geometry
    const int amat = lane >> 3;
    const int aRow = ((amat & 1) << 3) + (lane & 7);
    const uint32_t aKx = (uint32_t)(amat >> 1) << 4;
    uint32_t aAddrH[2], aAddrL[2];
    #pragma unroll
    for (int mf = 0; mf < 2; mf++) {
        const uint32_t roff = (uint32_t)(mw * 32 + mf * 16 + aRow) * PITCH + aKx;
        aAddrH[mf] = sb + SM_AHI + roff;
        aAddrL[mf] = sb + SM_ALO + roff;
    }
    const int bmat = (lane >> 3) & 1;
    const int bRow = lane & 7;
    const uint32_t bKx = (uint32_t)bmat << 4;
    uint32_t bAddrH[4], bAddrL[4];
    #pragma unroll
    for (int nf = 0; nf < 4; nf++) {
        const uint32_t roff = (uint32_t)(nw * 32 + nf * 8 + bRow) * PITCH + bKx;
        bAddrH[nf] = sb + SM_BHI + roff;
        bAddrL[nf] = sb + SM_BLO + roff;
    }

    #pragma unroll 1
    for (int ks = 0; ks < 8; ks++) {
        const uint32_t kb = (uint32_t)ks * 32;
        uint32_t ah[2][4], al[2][4], bh[4][2], bl[4][2];
        #pragma unroll
        for (int mf = 0; mf < 2; mf++) {
            ldm_x4(ah[mf], aAddrH[mf] + kb);
            ldm_x4(al[mf], aAddrL[mf] + kb);
        }
        #pragma unroll
        for (int nf = 0; nf < 4; nf++) {
            ldm_x2(bh[nf], bAddrH[nf] + kb);
            ldm_x2(bl[nf], bAddrL[nf] + kb);
        }
        #pragma unroll
        for (int mf = 0; mf < 2; mf++)
            #pragma unroll
            for (int nf = 0; nf < 4; nf++) {
                mma_bf16(acc[mf][nf], ah[mf], bh[nf]);
                mma_bf16(acc[mf][nf], ah[mf], bl[nf]);
                mma_bf16(acc[mf][nf], al[mf], bh[nf]);
            }
    }

    // ---- epilogue: write C (+ b1 fold for U half) ----
    const int rbase = m0 + mw * 32 + (lane >> 2);
    const int cq    = (lane & 3) * 2;
    #pragma unroll
    for (int mf = 0; mf < 2; mf++) {
        #pragma unroll
        for (int nf = 0; nf < 4; nf++) {
            const int gcol = nblk * 128 + nw * 32 + nf * 8 + cq;
            float2 bb = make_float2(0.f, 0.f);
            if (nblk < 2) bb = *(const float2*)(b1 + gcol);
            const int r0 = rbase + mf * 16;
            if (r0 < M) {
                float2 o = make_float2(acc[mf][nf][0] + bb.x, acc[mf][nf][1] + bb.y);
                *(float2*)(g_uv + (size_t)r0 * 512 + gcol) = o;
            }
            if (r0 + 8 < M) {
                float2 o = make_float2(acc[mf][nf][2] + bb.x, acc[mf][nf][3] + bb.y);
                *(float2*)(g_uv + (size_t)(r0 + 8) * 512 + gcol) = o;
            }
        }
    }
}

// ---------------------------------------------------------------------------
// Kernel 2: per-edge MLP tail.  TWO edges per warp (MLP 4 -> 8).
// ---------------------------------------------------------------------------
__global__ __launch_bounds__(256)
void edge_mlp_kernel(const int* __restrict__ ei,
                     const float* __restrict__ W2,
                     const float* __restrict__ b2,
                     float* __restrict__ out, int E, int N)
{
    __shared__ float4 sW2[64];
    const int tid = threadIdx.x;
    if (tid < 64) sW2[tid] = ((const float4*)W2)[tid];
    __syncthreads();

    const int warp = tid >> 5;
    const int lane = tid & 31;
    const int e0 = (blockIdx.x * 8 + warp) * 2;
    if (e0 >= E) return;
    const bool has1 = (e0 + 1) < E;
    const int hi = N - 1;

    int r0 = ei[e0], c0 = ei[E + e0];
    int r1 = has1 ? ei[e0 + 1] : 0;
    int c1 = has1 ? ei[E + e0 + 1] : 0;
    r0 = r0 < 0 ? 0 : (r0 > hi ? hi : r0);
    c0 = c0 < 0 ? 0 : (c0 > hi ? hi : c0);
    r1 = r1 < 0 ? 0 : (r1 > hi ? hi : r1);
    c1 = c1 < 0 ? 0 : (c1 > hi ? hi : c1);

    const float4* u0p = (const float4*)(g_uv + (size_t)r0 * 512);
    const float4* v0p = (const float4*)(g_uv + (size_t)c0 * 512 + 256);
    const float4* u1p = (const float4*)(g_uv + (size_t)r1 * 512);
    const float4* v1p = (const float4*)(g_uv + (size_t)c1 * 512 + 256);

    // issue all 8 gathers up front (MLP=8)
    const int j0 = lane, j1 = lane + 32;
    float4 u0a = u0p[j0], u0b = u0p[j1];
    float4 v0a = v0p[j0], v0b = v0p[j1];
    float4 u1a = u1p[j0], u1b = u1p[j1];
    float4 v1a = v1p[j0], v1b = v1p[j1];
    const float4 wa = sW2[j0], wb = sW2[j1];

    float a0 = 0.f, a1 = 0.f;
    a0 = fmaf(fmaxf(u0a.x + v0a.x, 0.f), wa.x, a0);
    a0 = fmaf(fmaxf(u0a.y + v0a.y, 0.f), wa.y, a0);
    a0 = fmaf(fmaxf(u0a.z + v0a.z, 0.f), wa.z, a0);
    a0 = fmaf(fmaxf(u0a.w + v0a.w, 0.f), wa.w, a0);
    a0 = fmaf(fmaxf(u0b.x + v0b.x, 0.f), wb.x, a0);
    a0 = fmaf(fmaxf(u0b.y + v0b.y, 0.f), wb.y, a0);
    a0 = fmaf(fmaxf(u0b.z + v0b.z, 0.f), wb.z, a0);
    a0 = fmaf(fmaxf(u0b.w + v0b.w, 0.f), wb.w, a0);
    a1 = fmaf(fmaxf(u1a.x + v1a.x, 0.f), wa.x, a1);
    a1 = fmaf(fmaxf(u1a.y + v1a.y, 0.f), wa.y, a1);
    a1 = fmaf(fmaxf(u1a.z + v1a.z, 0.f), wa.z, a1);
    a1 = fmaf(fmaxf(u1a.w + v1a.w, 0.f), wa.w, a1);
    a1 = fmaf(fmaxf(u1b.x + v1b.x, 0.f), wb.x, a1);
    a1 = fmaf(fmaxf(u1b.y + v1b.y, 0.f), wb.y, a1);
    a1 = fmaf(fmaxf(u1b.z + v1b.z, 0.f), wb.z, a1);
    a1 = fmaf(fmaxf(u1b.w + v1b.w, 0.f), wb.w, a1);

    #pragma unroll
    for (int off = 16; off; off >>= 1) {
        a0 += __shfl_xor_sync(0xFFFFFFFFu, a0, off);
        a1 += __shfl_xor_sync(0xFFFFFFFFu, a1, off);
    }

    if (lane == 0) {
        float w = fmaxf(a0 + b2[0], 0.f);
        out[e0] = (w < 0.05f) ? 0.f : w;
        if (has1) {
            float w1 = fmaxf(a1 + b2[0], 0.f);
            out[e0 + 1] = (w1 < 0.05f) ? 0.f : w1;
        }
    }
}

// ---------------------------------------------------------------------------
// Host (proven size-based input mapping).
// ---------------------------------------------------------------------------
extern "C" void kernel_launch(void* const* d_in, const int* in_sizes, int n_in,
                              void* d_out, int out_size)
{
    int ord[16];
    for (int i = 0; i < n_in; i++) ord[i] = i;
    for (int i = 0; i < n_in; i++)
        for (int j = i + 1; j < n_in; j++)
            if (in_sizes[ord[j]] > in_sizes[ord[i]]) { int t = ord[i]; ord[i] = ord[j]; ord[j] = t; }

    const int idx_emb = ord[0];
    const int idx_ei  = ord[1];
    const int idx_W1  = ord[2];
    const int idx_b2  = ord[n_in - 1];
    int idx_b1 = -1, idx_W2 = -1;
    for (int i = 0; i < n_in; i++) {
        if (i == idx_emb || i == idx_ei || i == idx_W1 || i == idx_b2) continue;
        if (idx_b1 < 0) idx_b1 = i; else idx_W2 = i;
    }

    const float* emb = (const float*)d_in[idx_emb];  // [N,128]
    const int*   ei  = (const int*)d_in[idx_ei];     // [2,E] int32
    const float* W1  = (const float*)d_in[idx_W1];   // [256,256]
    const float* b1  = (const float*)d_in[idx_b1];   // [256]
    const float* W2  = (const float*)d_in[idx_W2];   // [256,1]
    const float* b2  = (const float*)d_in[idx_b2];   // [1]
    float*       out = (float*)d_out;

    int N = in_sizes[idx_emb] / 128;
    if (N > UV_MAX_ROWS) N = UV_MAX_ROWS;
    const int E = in_sizes[idx_ei] / 2;

    cudaFuncSetAttribute(uv_mma_kernel,
                         cudaFuncAttributeMaxDynamicSharedMemorySize, SM_TOTAL);

    bsplit_kernel<<<256, 256>>>(W1);
    asplit_kernel<<<(N * 32 + 255) / 256, 256>>>(emb, N);

    dim3 ggrid(4, (N + 63) / 64);
    uv_mma_kernel<<<ggrid, 256, SM_TOTAL>>>(b1, N);

    const int blocks = (E + 15) / 16;
    edge_mlp_kernel<<<blocks, 256>>>(ei, W2, b2, out, E, N);
}

// round 12
// speedup vs baseline: 1.6077x; 1.3230x over previous
#include <cuda_runtime.h>
#include <cuda_bf16.h>
#include <cstdint>

// ---------------- scratch ----------------
#define UV_MAX_ROWS 131072
__device__ float g_uv[(size_t)UV_MAX_ROWS * 512];
// W1 split bf16 hi/lo, K-major: [half][n(256)][k(128)]
__device__ __nv_bfloat16 g_bhi[2][256][128];
__device__ __nv_bfloat16 g_blo[2][256][128];
// A (emb) split bf16 hi/lo, row-major [row][k(128)]
__device__ __nv_bfloat16 g_ahi[UV_MAX_ROWS][128];
__device__ __nv_bfloat16 g_alo[UV_MAX_ROWS][128];

__device__ __forceinline__ uint32_t smem_u32(const void* p) {
    uint32_t a;
    asm("{ .reg .u64 t; cvta.to.shared.u64 t, %1; cvt.u32.u64 %0, t; }" : "=r"(a) : "l"(p));
    return a;
}
__device__ __forceinline__ void cp16(uint32_t dst, const void* src) {
    asm volatile("cp.async.cg.shared.global [%0], [%1], 16;" :: "r"(dst), "l"(src));
}
__device__ __forceinline__ void cp_commit_wait() {
    asm volatile("cp.async.commit_group;" ::: "memory");
    asm volatile("cp.async.wait_group 0;" ::: "memory");
}
__device__ __forceinline__ void ldm_x4(uint32_t* r, uint32_t addr) {
    asm volatile("ldmatrix.sync.aligned.m8n8.x4.shared.b16 {%0,%1,%2,%3}, [%4];"
                 : "=r"(r[0]), "=r"(r[1]), "=r"(r[2]), "=r"(r[3]) : "r"(addr));
}
__device__ __forceinline__ void mma_bf16(float* c, const uint32_t* a, const uint32_t* b) {
    asm volatile("mma.sync.aligned.m16n8k16.row.col.f32.bf16.bf16.f32 "
                 "{%0,%1,%2,%3}, {%4,%5,%6,%7}, {%8,%9}, {%0,%1,%2,%3};"
                 : "+f"(c[0]), "+f"(c[1]), "+f"(c[2]), "+f"(c[3])
                 : "r"(a[0]), "r"(a[1]), "r"(a[2]), "r"(a[3]), "r"(b[0]), "r"(b[1]));
}

// SMEM: bf16 tiles, 272-byte row pitch (256B data + 16B pad => conflict-free ldmatrix)
#define PITCH 272
#define SM_AHI 0u
#define SM_ALO 17408u
#define SM_BHI 34816u
#define SM_BLO 69632u
#define SM_TOTAL 104448

// ---------------------------------------------------------------------------
// Kernel 0a: split W1 -> bf16 hi/lo K-major (one shot).
// ---------------------------------------------------------------------------
__global__ void bsplit_kernel(const float* __restrict__ W1)
{
    int idx  = blockIdx.x * 256 + threadIdx.x;     // 0..65535
    int half = idx >> 15;
    int k    = (idx >> 8) & 127;
    int n    = idx & 255;
    float v = W1[(half * 128 + k) * 256 + n];
    __nv_bfloat16 hi = __float2bfloat16(v);
    __nv_bfloat16 lo = __float2bfloat16(v - __bfloat162float(hi));
    g_bhi[half][n][k] = hi;
    g_blo[half][n][k] = lo;
}

// ---------------------------------------------------------------------------
// Kernel 0b: split A (emb) -> bf16 hi/lo row-major. One float4 per thread.
// ---------------------------------------------------------------------------
__global__ void asplit_kernel(const float* __restrict__ A, int M)
{
    int idx = blockIdx.x * 256 + threadIdx.x;      // over M*32 float4 groups
    if (idx >= M * 32) return;
    int row = idx >> 5;
    int k0  = (idx & 31) * 4;
    float4 v = *(const float4*)(A + (size_t)row * 128 + k0);
    __nv_bfloat162 h01 = __floats2bfloat162_rn(v.x, v.y);
    __nv_bfloat162 h23 = __floats2bfloat162_rn(v.z, v.w);
    __nv_bfloat162 l01 = __floats2bfloat162_rn(
        v.x - __bfloat162float(__low2bfloat16(h01)),
        v.y - __bfloat162float(__high2bfloat16(h01)));
    __nv_bfloat162 l23 = __floats2bfloat162_rn(
        v.z - __bfloat162float(__low2bfloat16(h23)),
        v.w - __bfloat162float(__high2bfloat16(h23)));
    uint2 ph, pl;
    ph.x = *(uint32_t*)&h01; ph.y = *(uint32_t*)&h23;
    pl.x = *(uint32_t*)&l01; pl.y = *(uint32_t*)&l23;
    *(uint2*)&g_ahi[row][k0] = ph;
    *(uint2*)&g_alo[row][k0] = pl;
}

// ---------------------------------------------------------------------------
// Kernel 1: split-bf16 GEMM via mma.sync.  CTA tile: 64 M-rows x 128 N-cols.
// C = Ahi*Bhi + Ahi*Blo + Alo*Bhi (fp32 accum). 102KB smem -> 2 CTAs/SM.
// grid.x = nblk 0..3 (cols 0..511; nblk<2 -> U with b1 fold).
// 8 warps: warp (mw = wid&1 -> 32 rows, nw = wid>>1 -> 32 cols).
// B fragments fetched with ldmatrix.x4: one x4 covers a 16-col pair at
// k0/k8 -> regs {r0,r2} = even n-8-block, {r1,r3} = odd n-8-block.
// ---------------------------------------------------------------------------
__global__ __launch_bounds__(256, 2)
void uv_mma_kernel(const float* __restrict__ b1, int M)
{
    extern __shared__ char smem[];
    const uint32_t sb = smem_u32(smem);
    const int tid  = threadIdx.x;
    const int wid  = tid >> 5;
    const int lane = tid & 31;
    const int nblk = blockIdx.x;
    const int m0   = blockIdx.y * 64;
    const int half  = nblk >> 1;
    const int nbase = (nblk & 1) * 128;

    // ---- cp.async tile loads (bf16, pre-split) ----
    for (int i = tid; i < 2048; i += 256) {        // A: 64 rows x 16 x 16B, hi+lo
        const int h   = i >> 10;
        const int row = (i >> 4) & 63;
        const int q   = i & 15;
        const uint32_t dst = sb + (h ? SM_ALO : SM_AHI) + row * PITCH + q * 16;
        const __nv_bfloat16* src = (h ? g_alo : g_ahi)[m0 + row] + q * 8;
        cp16(dst, src);
    }
    for (int i = tid; i < 4096; i += 256) {        // B: 128 rows x 16 x 16B, hi+lo
        const int h = i >> 11;
        const int n = (i >> 4) & 127;
        const int q = i & 15;
        const uint32_t dst = sb + (h ? SM_BLO : SM_BHI) + n * PITCH + q * 16;
        const __nv_bfloat16* src = (h ? g_blo : g_bhi)[half][nbase + n] + q * 8;
        cp16(dst, src);
    }
    cp_commit_wait();
    __syncthreads();

    const int mw = wid & 1;        // 32 rows each
    const int nw = wid >> 1;       // 32 cols each

    float acc[2][4][4];
    #pragma unroll
    for (int i = 0; i < 2; i++)
        #pragma unroll
        for (int j = 0; j < 4; j++)
            #pragma unroll
            for (int q = 0; q < 4; q++) acc[i][j][q] = 0.f;

    // A ldmatrix geometry (x4: [m,k0],[m+8,k0],[m,k8],[m+8,k8])
    const int amat = lane >> 3;
    const int aRow = ((amat & 1) << 3) + (lane & 7);
    const uint32_t aKx = (uint32_t)(amat >> 1) << 4;
    uint32_t aAddrH[2], aAddrL[2];
    #pragma unroll
    for (int mf = 0; mf < 2; mf++) {
        const uint32_t roff = (uint32_t)(mw * 32 + mf * 16 + aRow) * PITCH + aKx;
        aAddrH[mf] = sb + SM_AHI + roff;
        aAddrL[mf] = sb + SM_ALO + roff;
    }
    // B ldmatrix.x4 geometry over a 16-col pair:
    //   row = pairbase + ((lane>>3)&1)*8 + (lane&7), koff = (lane>>4)*16
    const int bRow = ((lane >> 3) & 1) * 8 + (lane & 7);
    const uint32_t bKx = (uint32_t)(lane >> 4) << 4;
    uint32_t bAddrH[2], bAddrL[2];
    #pragma unroll
    for (int pr = 0; pr < 2; pr++) {
        const uint32_t roff = (uint32_t)(nw * 32 + pr * 16 + bRow) * PITCH + bKx;
        bAddrH[pr] = sb + SM_BHI + roff;
        bAddrL[pr] = sb + SM_BLO + roff;
    }

    #pragma unroll 1
    for (int ks = 0; ks < 8; ks++) {
        const uint32_t kb = (uint32_t)ks * 32;
        uint32_t ah[2][4], al[2][4], bhp[2][4], blp[2][4];
        #pragma unroll
        for (int mf = 0; mf < 2; mf++) {
            ldm_x4(ah[mf], aAddrH[mf] + kb);
            ldm_x4(al[mf], aAddrL[mf] + kb);
        }
        #pragma unroll
        for (int pr = 0; pr < 2; pr++) {
            ldm_x4(bhp[pr], bAddrH[pr] + kb);
            ldm_x4(blp[pr], bAddrL[pr] + kb);
        }
        #pragma unroll
        for (int mf = 0; mf < 2; mf++)
            #pragma unroll
            for (int nf = 0; nf < 4; nf++) {
                const int pr = nf >> 1, od = nf & 1;
                uint32_t bh[2] = { bhp[pr][od], bhp[pr][od + 2] };
                uint32_t bl[2] = { blp[pr][od], blp[pr][od + 2] };
                mma_bf16(acc[mf][nf], ah[mf], bh);
                mma_bf16(acc[mf][nf], ah[mf], bl);
                mma_bf16(acc[mf][nf], al[mf], bh);
            }
    }

    // ---- epilogue: write C (+ b1 fold for U half) ----
    const int rbase = m0 + mw * 32 + (lane >> 2);
    const int cq    = (lane & 3) * 2;
    #pragma unroll
    for (int mf = 0; mf < 2; mf++) {
        #pragma unroll
        for (int nf = 0; nf < 4; nf++) {
            const int gcol = nblk * 128 + nw * 32 + nf * 8 + cq;
            float2 bb = make_float2(0.f, 0.f);
            if (nblk < 2) bb = *(const float2*)(b1 + gcol);
            const int r0 = rbase + mf * 16;
            if (r0 < M) {
                float2 o = make_float2(acc[mf][nf][0] + bb.x, acc[mf][nf][1] + bb.y);
                *(float2*)(g_uv + (size_t)r0 * 512 + gcol) = o;
            }
            if (r0 + 8 < M) {
                float2 o = make_float2(acc[mf][nf][2] + bb.x, acc[mf][nf][3] + bb.y);
                *(float2*)(g_uv + (size_t)(r0 + 8) * 512 + gcol) = o;
            }
        }
    }
}

// ---------------------------------------------------------------------------
// Kernel 2: per-edge MLP tail. ONE edge per warp (proven R6 config: 130 us,
// occ 80%, DRAM 72% — throughput governed by resident warps, not per-warp ILP).
// ---------------------------------------------------------------------------
__global__ __launch_bounds__(256)
void edge_mlp_kernel(const int* __restrict__ ei,
                     const float* __restrict__ W2,
                     const float* __restrict__ b2,
                     float* __restrict__ out, int E, int N)
{
    __shared__ float4 sW2[64];
    const int tid = threadIdx.x;
    if (tid < 64) sW2[tid] = ((const float4*)W2)[tid];
    __syncthreads();

    const int e = blockIdx.x * 8 + (tid >> 5);
    if (e >= E) return;
    const int lane = tid & 31;

    int r = ei[e];
    int c = ei[E + e];
    const int hi = N - 1;
    r = r < 0 ? 0 : (r > hi ? hi : r);
    c = c < 0 ? 0 : (c > hi ? hi : c);

    const float4* u4 = (const float4*)(g_uv + (size_t)r * 512);
    const float4* v4 = (const float4*)(g_uv + (size_t)c * 512 + 256);

    float acc = 0.f;
    #pragma unroll
    for (int i = 0; i < 2; i++) {
        const int j = lane + 32 * i;
        const float4 u = u4[j];
        const float4 v = v4[j];
        const float4 w = sW2[j];
        acc = fmaf(fmaxf(u.x + v.x, 0.f), w.x, acc);
        acc = fmaf(fmaxf(u.y + v.y, 0.f), w.y, acc);
        acc = fmaf(fmaxf(u.z + v.z, 0.f), w.z, acc);
        acc = fmaf(fmaxf(u.w + v.w, 0.f), w.w, acc);
    }

    #pragma unroll
    for (int off = 16; off; off >>= 1)
        acc += __shfl_xor_sync(0xFFFFFFFFu, acc, off);

    if (lane == 0) {
        float w = fmaxf(acc + b2[0], 0.f);
        out[e] = (w < 0.05f) ? 0.f : w;
    }
}

// ---------------------------------------------------------------------------
// Host (proven size-based input mapping).
// ---------------------------------------------------------------------------
extern "C" void kernel_launch(void* const* d_in, const int* in_sizes, int n_in,
                              void* d_out, int out_size)
{
    int ord[16];
    for (int i = 0; i < n_in; i++) ord[i] = i;
    for (int i = 0; i < n_in; i++)
        for (int j = i + 1; j < n_in; j++)
            if (in_sizes[ord[j]] > in_sizes[ord[i]]) { int t = ord[i]; ord[i] = ord[j]; ord[j] = t; }

    const int idx_emb = ord[0];
    const int idx_ei  = ord[1];
    const int idx_W1  = ord[2];
    const int idx_b2  = ord[n_in - 1];
    int idx_b1 = -1, idx_W2 = -1;
    for (int i = 0; i < n_in; i++) {
        if (i == idx_emb || i == idx_ei || i == idx_W1 || i == idx_b2) continue;
        if (idx_b1 < 0) idx_b1 = i; else idx_W2 = i;
    }

    const float* emb = (const float*)d_in[idx_emb];  // [N,128]
    const int*   ei  = (const int*)d_in[idx_ei];     // [2,E] int32
    const float* W1  = (const float*)d_in[idx_W1];   // [256,256]
    const float* b1  = (const float*)d_in[idx_b1];   // [256]
    const float* W2  = (const float*)d_in[idx_W2];   // [256,1]
    const float* b2  = (const float*)d_in[idx_b2];   // [1]
    float*       out = (float*)d_out;

    int N = in_sizes[idx_emb] / 128;
    if (N > UV_MAX_ROWS) N = UV_MAX_ROWS;
    const int E = in_sizes[idx_ei] / 2;

    cudaFuncSetAttribute(uv_mma_kernel,
                         cudaFuncAttributeMaxDynamicSharedMemorySize, SM_TOTAL);

    bsplit_kernel<<<256, 256>>>(W1);
    asplit_kernel<<<(N * 32 + 255) / 256, 256>>>(emb, N);

    dim3 ggrid(4, (N + 63) / 64);
    uv_mma_kernel<<<ggrid, 256, SM_TOTAL>>>(b1, N);

    const int blocks = (E + 7) / 8;
    edge_mlp_kernel<<<blocks, 256>>>(ei, W2, b2, out, E, N);
}

// round 14
// speedup vs baseline: 1.6169x; 1.0057x over previous
#include <cuda_runtime.h>
#include <cuda_bf16.h>
#include <cstdint>

// ---------------- scratch ----------------
#define UV_MAX_ROWS 131072
__device__ float g_uv[(size_t)UV_MAX_ROWS * 512];
// W1 split bf16 hi/lo, K-major: [half][n(256)][k(128)]
__device__ __nv_bfloat16 g_bhi[2][256][128];
__device__ __nv_bfloat16 g_blo[2][256][128];
// A (emb) split bf16 hi/lo, row-major [row][k(128)]
__device__ __nv_bfloat16 g_ahi[UV_MAX_ROWS][128];
__device__ __nv_bfloat16 g_alo[UV_MAX_ROWS][128];

__device__ __forceinline__ uint32_t smem_u32(const void* p) {
    uint32_t a;
    asm("{ .reg .u64 t; cvta.to.shared.u64 t, %1; cvt.u32.u64 %0, t; }" : "=r"(a) : "l"(p));
    return a;
}
__device__ __forceinline__ void cp16(uint32_t dst, const void* src) {
    asm volatile("cp.async.cg.shared.global [%0], [%1], 16;" :: "r"(dst), "l"(src));
}
__device__ __forceinline__ void cp_commit_wait() {
    asm volatile("cp.async.commit_group;" ::: "memory");
    asm volatile("cp.async.wait_group 0;" ::: "memory");
}
__device__ __forceinline__ void ldm_x4(uint32_t* r, uint32_t addr) {
    asm volatile("ldmatrix.sync.aligned.m8n8.x4.shared.b16 {%0,%1,%2,%3}, [%4];"
                 : "=r"(r[0]), "=r"(r[1]), "=r"(r[2]), "=r"(r[3]) : "r"(addr));
}
__device__ __forceinline__ void mma_bf16(float* c, const uint32_t* a, const uint32_t* b) {
    asm volatile("mma.sync.aligned.m16n8k16.row.col.f32.bf16.bf16.f32 "
                 "{%0,%1,%2,%3}, {%4,%5,%6,%7}, {%8,%9}, {%0,%1,%2,%3};"
                 : "+f"(c[0]), "+f"(c[1]), "+f"(c[2]), "+f"(c[3])
                 : "r"(a[0]), "r"(a[1]), "r"(a[2]), "r"(a[3]), "r"(b[0]), "r"(b[1]));
}
// L2 evict_last gather (keeps UV table resident vs streaming data)
__device__ __forceinline__ float4 ldg_el(const float4* p, unsigned long long pol) {
    float4 v;
    asm volatile("ld.global.nc.L2::cache_hint.v4.f32 {%0,%1,%2,%3}, [%4], %5;"
                 : "=f"(v.x), "=f"(v.y), "=f"(v.z), "=f"(v.w)
                 : "l"(p), "l"(pol));
    return v;
}

// SMEM: bf16 tiles, 272-byte row pitch (256B data + 16B pad => conflict-free ldmatrix)
#define PITCH 272
#define SM_AHI 0u
#define SM_ALO 17408u
#define SM_BHI 34816u
#define SM_BLO 69632u
#define SM_TOTAL 104448

// ---------------------------------------------------------------------------
// Kernel 0: fused split.  idx < 65536 -> W1 -> g_b{hi,lo} (K-major);
// remaining idx -> A float4 groups -> g_a{hi,lo}.
// ---------------------------------------------------------------------------
__global__ void split_kernel(const float* __restrict__ W1,
                             const float* __restrict__ A, int M)
{
    int idx = blockIdx.x * 256 + threadIdx.x;
    if (idx < 65536) {
        int half = idx >> 15;
        int k    = (idx >> 8) & 127;
        int n    = idx & 255;
        float v = W1[(half * 128 + k) * 256 + n];
        __nv_bfloat16 hi = __float2bfloat16(v);
        __nv_bfloat16 lo = __float2bfloat16(v - __bfloat162float(hi));
        g_bhi[half][n][k] = hi;
        g_blo[half][n][k] = lo;
        return;
    }
    int a = idx - 65536;                     // A float4 group
    if (a >= M * 32) return;
    int row = a >> 5;
    int k0  = (a & 31) * 4;
    float4 v = *(const float4*)(A + (size_t)row * 128 + k0);
    __nv_bfloat162 h01 = __floats2bfloat162_rn(v.x, v.y);
    __nv_bfloat162 h23 = __floats2bfloat162_rn(v.z, v.w);
    __nv_bfloat162 l01 = __floats2bfloat162_rn(
        v.x - __bfloat162float(__low2bfloat16(h01)),
        v.y - __bfloat162float(__high2bfloat16(h01)));
    __nv_bfloat162 l23 = __floats2bfloat162_rn(
        v.z - __bfloat162float(__low2bfloat16(h23)),
        v.w - __bfloat162float(__high2bfloat16(h23)));
    uint2 ph, pl;
    ph.x = *(uint32_t*)&h01; ph.y = *(uint32_t*)&h23;
    pl.x = *(uint32_t*)&l01; pl.y = *(uint32_t*)&l23;
    *(uint2*)&g_ahi[row][k0] = ph;
    *(uint2*)&g_alo[row][k0] = pl;
}

// ---------------------------------------------------------------------------
// Kernel 1: split-bf16 GEMM via mma.sync.  CTA tile: 64 M-rows x 128 N-cols.
// C = Ahi*Bhi + Ahi*Blo + Alo*Bhi (fp32 accum). 102KB smem -> 2 CTAs/SM.
// At the quarter-rate HMMA pipe floor (~271 TF/s bf16) — do not add issue work.
// ---------------------------------------------------------------------------
__global__ __launch_bounds__(256, 2)
void uv_mma_kernel(const float* __restrict__ b1, int M)
{
    extern __shared__ char smem[];
    const uint32_t sb = smem_u32(smem);
    const int tid  = threadIdx.x;
    const int wid  = tid >> 5;
    const int lane = tid & 31;
    const int nblk = blockIdx.x;
    const int m0   = blockIdx.y * 64;
    const int half  = nblk >> 1;
    const int nbase = (nblk & 1) * 128;

    for (int i = tid; i < 2048; i += 256) {        // A: 64 rows x 16 x 16B, hi+lo
        const int h   = i >> 10;
        const int row = (i >> 4) & 63;
        const int q   = i & 15;
        const uint32_t dst = sb + (h ? SM_ALO : SM_AHI) + row * PITCH + q * 16;
        const __nv_bfloat16* src = (h ? g_alo : g_ahi)[m0 + row] + q * 8;
        cp16(dst, src);
    }
    for (int i = tid; i < 4096; i += 256) {        // B: 128 rows x 16 x 16B, hi+lo
        const int h = i >> 11;
        const int n = (i >> 4) & 127;
        const int q = i & 15;
        const uint32_t dst = sb + (h ? SM_BLO : SM_BHI) + n * PITCH + q * 16;
        const __nv_bfloat16* src = (h ? g_blo : g_bhi)[half][nbase + n] + q * 8;
        cp16(dst, src);
    }
    cp_commit_wait();
    __syncthreads();

    const int mw = wid & 1;        // 32 rows each
    const int nw = wid >> 1;       // 32 cols each

    float acc[2][4][4];
    #pragma unroll
    for (int i = 0; i < 2; i++)
        #pragma unroll
        for (int j = 0; j < 4; j++)
            #pragma unroll
            for (int q = 0; q < 4; q++) acc[i][j][q] = 0.f;

    const int amat = lane >> 3;
    const int aRow = ((amat & 1) << 3) + (lane & 7);
    const uint32_t aKx = (uint32_t)(amat >> 1) << 4;
    uint32_t aAddrH[2], aAddrL[2];
    #pragma unroll
    for (int mf = 0; mf < 2; mf++) {
        const uint32_t roff = (uint32_t)(mw * 32 + mf * 16 + aRow) * PITCH + aKx;
        aAddrH[mf] = sb + SM_AHI + roff;
        aAddrL[mf] = sb + SM_ALO + roff;
    }
    const int bRow = ((lane >> 3) & 1) * 8 + (lane & 7);
    const uint32_t bKx = (uint32_t)(lane >> 4) << 4;
    uint32_t bAddrH[2], bAddrL[2];
    #pragma unroll
    for (int pr = 0; pr < 2; pr++) {
        const uint32_t roff = (uint32_t)(nw * 32 + pr * 16 + bRow) * PITCH + bKx;
        bAddrH[pr] = sb + SM_BHI + roff;
        bAddrL[pr] = sb + SM_BLO + roff;
    }

    #pragma unroll 1
    for (int ks = 0; ks < 8; ks++) {
        const uint32_t kb = (uint32_t)ks * 32;
        uint32_t ah[2][4], al[2][4], bhp[2][4], blp[2][4];
        #pragma unroll
        for (int mf = 0; mf < 2; mf++) {
            ldm_x4(ah[mf], aAddrH[mf] + kb);
            ldm_x4(al[mf], aAddrL[mf] + kb);
        }
        #pragma unroll
        for (int pr = 0; pr < 2; pr++) {
            ldm_x4(bhp[pr], bAddrH[pr] + kb);
            ldm_x4(blp[pr], bAddrL[pr] + kb);
        }
        #pragma unroll
        for (int mf = 0; mf < 2; mf++)
            #pragma unroll
            for (int nf = 0; nf < 4; nf++) {
                const int pr = nf >> 1, od = nf & 1;
                uint32_t bh[2] = { bhp[pr][od], bhp[pr][od + 2] };
                uint32_t bl[2] = { blp[pr][od], blp[pr][od + 2] };
                mma_bf16(acc[mf][nf], ah[mf], bh);
                mma_bf16(acc[mf][nf], ah[mf], bl);
                mma_bf16(acc[mf][nf], al[mf], bh);
            }
    }

    const int rbase = m0 + mw * 32 + (lane >> 2);
    const int cq    = (lane & 3) * 2;
    #pragma unroll
    for (int mf = 0; mf < 2; mf++) {
        #pragma unroll
        for (int nf = 0; nf < 4; nf++) {
            const int gcol = nblk * 128 + nw * 32 + nf * 8 + cq;
            float2 bb = make_float2(0.f, 0.f);
            if (nblk < 2) bb = *(const float2*)(b1 + gcol);
            const int r0 = rbase + mf * 16;
            if (r0 < M) {
                float2 o = make_float2(acc[mf][nf][0] + bb.x, acc[mf][nf][1] + bb.y);
                *(float2*)(g_uv + (size_t)r0 * 512 + gcol) = o;
            }
            if (r0 + 8 < M) {
                float2 o = make_float2(acc[mf][nf][2] + bb.x, acc[mf][nf][3] + bb.y);
                *(float2*)(g_uv + (size_t)(r0 + 8) * 512 + gcol) = o;
            }
        }
    }
}

// ---------------------------------------------------------------------------
// Kernel 2: per-edge MLP tail. ONE edge per warp (proven best), with
// L2 evict_last on the UV gathers to keep the 205MB table resident in L2.
// ---------------------------------------------------------------------------
__global__ __launch_bounds__(256)
void edge_mlp_kernel(const int* __restrict__ ei,
                     const float* __restrict__ W2,
                     const float* __restrict__ b2,
                     float* __restrict__ out, int E, int N)
{
    __shared__ float4 sW2[64];
    const int tid = threadIdx.x;
    if (tid < 64) sW2[tid] = ((const float4*)W2)[tid];
    __syncthreads();

    const int e = blockIdx.x * 8 + (tid >> 5);
    if (e >= E) return;
    const int lane = tid & 31;

    unsigned long long pol;
    asm("createpolicy.fractional.L2::evict_last.b64 %0, 1.0;" : "=l"(pol));

    int r = ei[e];
    int c = ei[E + e];
    const int hi = N - 1;
    r = r < 0 ? 0 : (r > hi ? hi : r);
    c = c < 0 ? 0 : (c > hi ? hi : c);

    const float4* u4 = (const float4*)(g_uv + (size_t)r * 512);
    const float4* v4 = (const float4*)(g_uv + (size_t)c * 512 + 256);

    float acc = 0.f;
    #pragma unroll
    for (int i = 0; i < 2; i++) {
        const int j = lane + 32 * i;
        const float4 u = ldg_el(u4 + j, pol);
        const float4 v = ldg_el(v4 + j, pol);
        const float4 w = sW2[j];
        acc = fmaf(fmaxf(u.x + v.x, 0.f), w.x, acc);
        acc = fmaf(fmaxf(u.y + v.y, 0.f), w.y, acc);
        acc = fmaf(fmaxf(u.z + v.z, 0.f), w.z, acc);
        acc = fmaf(fmaxf(u.w + v.w, 0.f), w.w, acc);
    }

    #pragma unroll
    for (int off = 16; off; off >>= 1)
        acc += __shfl_xor_sync(0xFFFFFFFFu, acc, off);

    if (lane == 0) {
        float w = fmaxf(acc + b2[0], 0.f);
        out[e] = (w < 0.05f) ? 0.f : w;
    }
}

// ---------------------------------------------------------------------------
// Host (proven size-based input mapping).
// ---------------------------------------------------------------------------
extern "C" void kernel_launch(void* const* d_in, const int* in_sizes, int n_in,
                              void* d_out, int out_size)
{
    int ord[16];
    for (int i = 0; i < n_in; i++) ord[i] = i;
    for (int i = 0; i < n_in; i++)
        for (int j = i + 1; j < n_in; j++)
            if (in_sizes[ord[j]] > in_sizes[ord[i]]) { int t = ord[i]; ord[i] = ord[j]; ord[j] = t; }

    const int idx_emb = ord[0];
    const int idx_ei  = ord[1];
    const int idx_W1  = ord[2];
    const int idx_b2  = ord[n_in - 1];
    int idx_b1 = -1, idx_W2 = -1;
    for (int i = 0; i < n_in; i++) {
        if (i == idx_emb || i == idx_ei || i == idx_W1 || i == idx_b2) continue;
        if (idx_b1 < 0) idx_b1 = i; else idx_W2 = i;
    }

    const float* emb = (const float*)d_in[idx_emb];  // [N,128]
    const int*   ei  = (const int*)d_in[idx_ei];     // [2,E] int32
    const float* W1  = (const float*)d_in[idx_W1];   // [256,256]
    const float* b1  = (const float*)d_in[idx_b1];   // [256]
    const float* W2  = (const float*)d_in[idx_W2];   // [256,1]
    const float* b2  = (const float*)d_in[idx_b2];   // [1]
    float*       out = (float*)d_out;

    int N = in_sizes[idx_emb] / 128;
    if (N > UV_MAX_ROWS) N = UV_MAX_ROWS;
    const int E = in_sizes[idx_ei] / 2;

    cudaFuncSetAttribute(uv_mma_kernel,
                         cudaFuncAttributeMaxDynamicSharedMemorySize, SM_TOTAL);

    const int split_items = 65536 + N * 32;
    split_kernel<<<(split_items + 255) / 256, 256>>>(W1, emb, N);

    dim3 ggrid(4, (N + 63) / 64);
    uv_mma_kernel<<<ggrid, 256, SM_TOTAL>>>(b1, N);

    const int blocks = (E + 7) / 8;
    edge_mlp_kernel<<<blocks, 256>>>(ei, W2, b2, out, E, N);
}

// round 15
// speedup vs baseline: 1.6971x; 1.0496x over previous
#include <cuda_runtime.h>
#include <cuda_bf16.h>
#include <cstdint>

// ---------------- scratch ----------------
#define UV_MAX_ROWS 131072
#define E_MAX 2097152
__device__ float g_uv[(size_t)UV_MAX_ROWS * 512];
__device__ __nv_bfloat16 g_bhi[2][256][128];
__device__ __nv_bfloat16 g_blo[2][256][128];
__device__ __nv_bfloat16 g_ahi[UV_MAX_ROWS][128];
__device__ __nv_bfloat16 g_alo[UV_MAX_ROWS][128];
// counting-sort workspace (rewritten every launch -> graph-replay safe)
__device__ int g_cnt[UV_MAX_ROWS];
__device__ int g_excl[UV_MAX_ROWS];
__device__ int g_bsum[512];
__device__ int g_start[UV_MAX_ROWS + 1];
__device__ int g_cursor[UV_MAX_ROWS];
__device__ int g_sc[E_MAX];
__device__ int g_se[E_MAX];

__device__ __forceinline__ uint32_t smem_u32(const void* p) {
    uint32_t a;
    asm("{ .reg .u64 t; cvta.to.shared.u64 t, %1; cvt.u32.u64 %0, t; }" : "=r"(a) : "l"(p));
    return a;
}
__device__ __forceinline__ void cp16(uint32_t dst, const void* src) {
    asm volatile("cp.async.cg.shared.global [%0], [%1], 16;" :: "r"(dst), "l"(src));
}
__device__ __forceinline__ void cp_commit_wait() {
    asm volatile("cp.async.commit_group;" ::: "memory");
    asm volatile("cp.async.wait_group 0;" ::: "memory");
}
__device__ __forceinline__ void ldm_x4(uint32_t* r, uint32_t addr) {
    asm volatile("ldmatrix.sync.aligned.m8n8.x4.shared.b16 {%0,%1,%2,%3}, [%4];"
                 : "=r"(r[0]), "=r"(r[1]), "=r"(r[2]), "=r"(r[3]) : "r"(addr));
}
__device__ __forceinline__ void mma_bf16(float* c, const uint32_t* a, const uint32_t* b) {
    asm volatile("mma.sync.aligned.m16n8k16.row.col.f32.bf16.bf16.f32 "
                 "{%0,%1,%2,%3}, {%4,%5,%6,%7}, {%8,%9}, {%0,%1,%2,%3};"
                 : "+f"(c[0]), "+f"(c[1]), "+f"(c[2]), "+f"(c[3])
                 : "r"(a[0]), "r"(a[1]), "r"(a[2]), "r"(a[3]), "r"(b[0]), "r"(b[1]));
}

#define PITCH 272
#define SM_AHI 0u
#define SM_ALO 17408u
#define SM_BHI 34816u
#define SM_BLO 69632u
#define SM_TOTAL 104448

// ---------------------------------------------------------------------------
// Kernel 0: fused split (W1 + A -> bf16 hi/lo), unchanged.
// ---------------------------------------------------------------------------
__global__ void split_kernel(const float* __restrict__ W1,
                             const float* __restrict__ A, int M)
{
    int idx = blockIdx.x * 256 + threadIdx.x;
    if (idx < 65536) {
        int half = idx >> 15;
        int k    = (idx >> 8) & 127;
        int n    = idx & 255;
        float v = W1[(half * 128 + k) * 256 + n];
        __nv_bfloat16 hi = __float2bfloat16(v);
        __nv_bfloat16 lo = __float2bfloat16(v - __bfloat162float(hi));
        g_bhi[half][n][k] = hi;
        g_blo[half][n][k] = lo;
        return;
    }
    int a = idx - 65536;
    if (a >= M * 32) return;
    int row = a >> 5;
    int k0  = (a & 31) * 4;
    float4 v = *(const float4*)(A + (size_t)row * 128 + k0);
    __nv_bfloat162 h01 = __floats2bfloat162_rn(v.x, v.y);
    __nv_bfloat162 h23 = __floats2bfloat162_rn(v.z, v.w);
    __nv_bfloat162 l01 = __floats2bfloat162_rn(
        v.x - __bfloat162float(__low2bfloat16(h01)),
        v.y - __bfloat162float(__high2bfloat16(h01)));
    __nv_bfloat162 l23 = __floats2bfloat162_rn(
        v.z - __bfloat162float(__low2bfloat16(h23)),
        v.w - __bfloat162float(__high2bfloat16(h23)));
    uint2 ph, pl;
    ph.x = *(uint32_t*)&h01; ph.y = *(uint32_t*)&h23;
    pl.x = *(uint32_t*)&l01; pl.y = *(uint32_t*)&l23;
    *(uint2*)&g_ahi[row][k0] = ph;
    *(uint2*)&g_alo[row][k0] = pl;
}

// ---------------------------------------------------------------------------
// Kernel 1: split-bf16 GEMM (proven, at quarter-rate HMMA pipe floor).
// ---------------------------------------------------------------------------
__global__ __launch_bounds__(256, 2)
void uv_mma_kernel(const float* __restrict__ b1, int M)
{
    extern __shared__ char smem[];
    const uint32_t sb = smem_u32(smem);
    const int tid  = threadIdx.x;
    const int wid  = tid >> 5;
    const int lane = tid & 31;
    const int nblk = blockIdx.x;
    const int m0   = blockIdx.y * 64;
    const int half  = nblk >> 1;
    const int nbase = (nblk & 1) * 128;

    for (int i = tid; i < 2048; i += 256) {
        const int h   = i >> 10;
        const int row = (i >> 4) & 63;
        const int q   = i & 15;
        const uint32_t dst = sb + (h ? SM_ALO : SM_AHI) + row * PITCH + q * 16;
        const __nv_bfloat16* src = (h ? g_alo : g_ahi)[m0 + row] + q * 8;
        cp16(dst, src);
    }
    for (int i = tid; i < 4096; i += 256) {
        const int h = i >> 11;
        const int n = (i >> 4) & 127;
        const int q = i & 15;
        const uint32_t dst = sb + (h ? SM_BLO : SM_BHI) + n * PITCH + q * 16;
        const __nv_bfloat16* src = (h ? g_blo : g_bhi)[half][nbase + n] + q * 8;
        cp16(dst, src);
    }
    cp_commit_wait();
    __syncthreads();

    const int mw = wid & 1;
    const int nw = wid >> 1;

    float acc[2][4][4];
    #pragma unroll
    for (int i = 0; i < 2; i++)
        #pragma unroll
        for (int j = 0; j < 4; j++)
            #pragma unroll
            for (int q = 0; q < 4; q++) acc[i][j][q] = 0.f;

    const int amat = lane >> 3;
    const int aRow = ((amat & 1) << 3) + (lane & 7);
    const uint32_t aKx = (uint32_t)(amat >> 1) << 4;
    uint32_t aAddrH[2], aAddrL[2];
    #pragma unroll
    for (int mf = 0; mf < 2; mf++) {
        const uint32_t roff = (uint32_t)(mw * 32 + mf * 16 + aRow) * PITCH + aKx;
        aAddrH[mf] = sb + SM_AHI + roff;
        aAddrL[mf] = sb + SM_ALO + roff;
    }
    const int bRow = ((lane >> 3) & 1) * 8 + (lane & 7);
    const uint32_t bKx = (uint32_t)(lane >> 4) << 4;
    uint32_t bAddrH[2], bAddrL[2];
    #pragma unroll
    for (int pr = 0; pr < 2; pr++) {
        const uint32_t roff = (uint32_t)(nw * 32 + pr * 16 + bRow) * PITCH + bKx;
        bAddrH[pr] = sb + SM_BHI + roff;
        bAddrL[pr] = sb + SM_BLO + roff;
    }

    #pragma unroll 1
    for (int ks = 0; ks < 8; ks++) {
        const uint32_t kb = (uint32_t)ks * 32;
        uint32_t ah[2][4], al[2][4], bhp[2][4], blp[2][4];
        #pragma unroll
        for (int mf = 0; mf < 2; mf++) {
            ldm_x4(ah[mf], aAddrH[mf] + kb);
            ldm_x4(al[mf], aAddrL[mf] + kb);
        }
        #pragma unroll
        for (int pr = 0; pr < 2; pr++) {
            ldm_x4(bhp[pr], bAddrH[pr] + kb);
            ldm_x4(blp[pr], bAddrL[pr] + kb);
        }
        #pragma unroll
        for (int mf = 0; mf < 2; mf++)
            #pragma unroll
            for (int nf = 0; nf < 4; nf++) {
                const int pr = nf >> 1, od = nf & 1;
                uint32_t bh[2] = { bhp[pr][od], bhp[pr][od + 2] };
                uint32_t bl[2] = { blp[pr][od], blp[pr][od + 2] };
                mma_bf16(acc[mf][nf], ah[mf], bh);
                mma_bf16(acc[mf][nf], ah[mf], bl);
                mma_bf16(acc[mf][nf], al[mf], bh);
            }
    }

    const int rbase = m0 + mw * 32 + (lane >> 2);
    const int cq    = (lane & 3) * 2;
    #pragma unroll
    for (int mf = 0; mf < 2; mf++) {
        #pragma unroll
        for (int nf = 0; nf < 4; nf++) {
            const int gcol = nblk * 128 + nw * 32 + nf * 8 + cq;
            float2 bb = make_float2(0.f, 0.f);
            if (nblk < 2) bb = *(const float2*)(b1 + gcol);
            const int r0 = rbase + mf * 16;
            if (r0 < M) {
                float2 o = make_float2(acc[mf][nf][0] + bb.x, acc[mf][nf][1] + bb.y);
                *(float2*)(g_uv + (size_t)r0 * 512 + gcol) = o;
            }
            if (r0 + 8 < M) {
                float2 o = make_float2(acc[mf][nf][2] + bb.x, acc[mf][nf][3] + bb.y);
                *(float2*)(g_uv + (size_t)(r0 + 8) * 512 + gcol) = o;
            }
        }
    }
}

// ---------------------------------------------------------------------------
// Counting sort of edges by source node r (all buffers rewritten per launch).
// ---------------------------------------------------------------------------
__global__ void k_zero(int N)
{
    int i = blockIdx.x * 256 + threadIdx.x;
    if (i < N) g_cnt[i] = 0;
}
__global__ void k_hist(const int* __restrict__ ei, int E, int N)
{
    int e = blockIdx.x * 256 + threadIdx.x;
    if (e >= E) return;
    int r = ei[e];
    r = r < 0 ? 0 : (r > N - 1 ? N - 1 : r);
    atomicAdd(&g_cnt[r], 1);
}
__global__ void k_scan1(int N)      // per-512-chunk exclusive scan + chunk totals
{
    __shared__ int sm[512];
    const int t = threadIdx.x;
    const int i = blockIdx.x * 512 + t;
    int x = (i < N) ? g_cnt[i] : 0;
    sm[t] = x;
    __syncthreads();
    #pragma unroll
    for (int off = 1; off < 512; off <<= 1) {
        int v = (t >= off) ? sm[t - off] : 0;
        __syncthreads();
        sm[t] += v;
        __syncthreads();
    }
    if (i < N) g_excl[i] = sm[t] - x;
    if (t == 511) g_bsum[blockIdx.x] = sm[511];
}
__global__ void k_scan2(int nb)     // exclusive scan of chunk totals (nb <= 512)
{
    __shared__ int sm[512];
    const int t = threadIdx.x;
    int x = (t < nb) ? g_bsum[t] : 0;
    sm[t] = x;
    __syncthreads();
    #pragma unroll
    for (int off = 1; off < 512; off <<= 1) {
        int v = (t >= off) ? sm[t - off] : 0;
        __syncthreads();
        sm[t] += v;
        __syncthreads();
    }
    if (t < nb) g_bsum[t] = sm[t] - x;
}
__global__ void k_scan3(int N, int E)   // add-back; init cursor; sentinel
{
    int i = blockIdx.x * 256 + threadIdx.x;
    if (i >= N) return;
    int s = g_excl[i] + g_bsum[i >> 9];
    g_start[i]  = s;
    g_cursor[i] = s;
    if (i == 0) g_start[N] = E;
}
__global__ void k_scatter(const int* __restrict__ ei, int E, int N)
{
    int e = blockIdx.x * 256 + threadIdx.x;
    if (e >= E) return;
    int r = ei[e];
    r = r < 0 ? 0 : (r > N - 1 ? N - 1 : r);
    int pos = atomicAdd(&g_cursor[r], 1);
    g_sc[pos] = ei[E + e];
    g_se[pos] = e;
}

// ---------------------------------------------------------------------------
// Kernel 2: warp-per-node edge MLP.  U[r] loaded ONCE into registers, then
// loop over this node's edges loading only V[c].  Per-edge dot order is
// identical to the previous kernel -> bitwise-identical output.
// ---------------------------------------------------------------------------
__global__ __launch_bounds__(256)
void edge_mlp_kernel(const float* __restrict__ W2,
                     const float* __restrict__ b2,
                     float* __restrict__ out, int E, int N)
{
    __shared__ float4 sW2[64];
    const int tid = threadIdx.x;
    if (tid < 64) sW2[tid] = ((const float4*)W2)[tid];
    __syncthreads();

    const int r = blockIdx.x * 8 + (tid >> 5);
    if (r >= N) return;
    const int lane = tid & 31;

    const int s = g_start[r];
    const int t = g_start[r + 1];
    if (s == t) return;

    const float4* u4 = (const float4*)(g_uv + (size_t)r * 512);
    const float4 ua = u4[lane];
    const float4 ub = u4[lane + 32];
    const float4 wa = sW2[lane];
    const float4 wb = sW2[lane + 32];
    const float bias = b2[0];
    const int hi = N - 1;

    for (int i = s; i < t; i++) {
        int c = g_sc[i];
        c = c < 0 ? 0 : (c > hi ? hi : c);
        const float4* v4 = (const float4*)(g_uv + (size_t)c * 512 + 256);
        const float4 va = v4[lane];
        const float4 vb = v4[lane + 32];

        float acc = 0.f;
        acc = fmaf(fmaxf(ua.x + va.x, 0.f), wa.x, acc);
        acc = fmaf(fmaxf(ua.y + va.y, 0.f), wa.y, acc);
        acc = fmaf(fmaxf(ua.z + va.z, 0.f), wa.z, acc);
        acc = fmaf(fmaxf(ua.w + va.w, 0.f), wa.w, acc);
        acc = fmaf(fmaxf(ub.x + vb.x, 0.f), wb.x, acc);
        acc = fmaf(fmaxf(ub.y + vb.y, 0.f), wb.y, acc);
        acc = fmaf(fmaxf(ub.z + vb.z, 0.f), wb.z, acc);
        acc = fmaf(fmaxf(ub.w + vb.w, 0.f), wb.w, acc);

        #pragma unroll
        for (int off = 16; off; off >>= 1)
            acc += __shfl_xor_sync(0xFFFFFFFFu, acc, off);

        if (lane == 0) {
            float w = fmaxf(acc + bias, 0.f);
            out[g_se[i]] = (w < 0.05f) ? 0.f : w;
        }
    }
}

// ---------------------------------------------------------------------------
// Host (proven size-based input mapping).
// ---------------------------------------------------------------------------
extern "C" void kernel_launch(void* const* d_in, const int* in_sizes, int n_in,
                              void* d_out, int out_size)
{
    int ord[16];
    for (int i = 0; i < n_in; i++) ord[i] = i;
    for (int i = 0; i < n_in; i++)
        for (int j = i + 1; j < n_in; j++)
            if (in_sizes[ord[j]] > in_sizes[ord[i]]) { int t = ord[i]; ord[i] = ord[j]; ord[j] = t; }

    const int idx_emb = ord[0];
    const int idx_ei  = ord[1];
    const int idx_W1  = ord[2];
    const int idx_b2  = ord[n_in - 1];
    int idx_b1 = -1, idx_W2 = -1;
    for (int i = 0; i < n_in; i++) {
        if (i == idx_emb || i == idx_ei || i == idx_W1 || i == idx_b2) continue;
        if (idx_b1 < 0) idx_b1 = i; else idx_W2 = i;
    }

    const float* emb = (const float*)d_in[idx_emb];  // [N,128]
    const int*   ei  = (const int*)d_in[idx_ei];     // [2,E] int32
    const float* W1  = (const float*)d_in[idx_W1];   // [256,256]
    const float* b1  = (const float*)d_in[idx_b1];   // [256]
    const float* W2  = (const float*)d_in[idx_W2];   // [256,1]
    const float* b2  = (const float*)d_in[idx_b2];   // [1]
    float*       out = (float*)d_out;

    int N = in_sizes[idx_emb] / 128;
    if (N > UV_MAX_ROWS) N = UV_MAX_ROWS;
    int E = in_sizes[idx_ei] / 2;
    if (E > E_MAX) E = E_MAX;

    cudaFuncSetAttribute(uv_mma_kernel,
                         cudaFuncAttributeMaxDynamicSharedMemorySize, SM_TOTAL);

    const int split_items = 65536 + N * 32;
    split_kernel<<<(split_items + 255) / 256, 256>>>(W1, emb, N);

    // edge counting sort (independent of UV values)
    const int gN = (N + 255) / 256, gE = (E + 255) / 256;
    const int nchunk = (N + 511) / 512;
    k_zero<<<gN, 256>>>(N);
    k_hist<<<gE, 256>>>(ei, E, N);
    k_scan1<<<nchunk, 512>>>(N);
    k_scan2<<<1, 512>>>(nchunk);
    k_scan3<<<gN, 256>>>(N, E);
    k_scatter<<<gE, 256>>>(ei, E, N);

    dim3 ggrid(4, (N + 63) / 64);
    uv_mma_kernel<<<ggrid, 256, SM_TOTAL>>>(b1, N);

    edge_mlp_kernel<<<(N + 7) / 8, 256>>>(W2, b2, out, E, N);
}